// round 13
// baseline (speedup 1.0000x reference)
#include <cuda_runtime.h>
#include <cuda_fp16.h>
#include <cstdint>
#include <math.h>

#define T_TOK 2048
#define HID   2048
#define INTER 1408
#define NEXP  8

#define GATE_SZ ((size_t)NEXP * INTER * HID)
#define SH_SZ   ((size_t)INTER * HID)
#define UP_OFF   (GATE_SZ)
#define DOWN_OFF (2 * GATE_SZ)
#define SG_OFF   (3 * GATE_SZ)
#define SU_OFF   (SG_OFF + SH_SZ)
#define SD_OFF   (SU_OFF + SH_SZ)
#define W16_TOTAL (SD_OFF + SH_SZ)

// ---------------- device scratch ----------------
__device__ __half g_w16[W16_TOTAL];
__device__ __half g_x16[(size_t)T_TOK * HID];
__device__ __half g_hmid[(size_t)(NEXP + 1) * T_TOK * INTER];
__device__ int    g_cnt[NEXP];          // zero-init at load; re-zeroed by combine tail
__device__ int    g_tok [NEXP * T_TOK];
__device__ int    g_slot[NEXP * T_TOK];
__device__ float  g_wt  [NEXP * T_TOK];
__device__ float  g_eo  [(size_t)2 * T_TOK * HID];

// ---------------- helpers ----------------
__device__ __forceinline__ uint32_t smem_u32(const void* p) {
    uint32_t a;
    asm("{ .reg .u64 t; cvta.to.shared.u64 t, %1; cvt.u32.u64 %0, t; }" : "=r"(a) : "l"(p));
    return a;
}
// 128B-row tile swizzle: 16B slot XOR (row&7) — conflict-free cp.async + ldmatrix
__device__ __forceinline__ uint32_t swz(int r, int cb) {
    return (uint32_t)((r << 7) + ((((cb >> 4) ^ (r & 7)) << 4) | (cb & 15)));
}
__device__ __forceinline__ void cpa(uint32_t dst, const void* src) {
    asm volatile("cp.async.cg.shared.global [%0], [%1], 16;" :: "r"(dst), "l"(src));
}
#define CP_COMMIT()  asm volatile("cp.async.commit_group;")
#define CP_WAIT1()   asm volatile("cp.async.wait_group 1;")

__device__ __forceinline__ void ldsm4(uint32_t* r, uint32_t a) {
    asm volatile("ldmatrix.sync.aligned.m8n8.x4.shared.b16 {%0,%1,%2,%3}, [%4];"
        : "=r"(r[0]), "=r"(r[1]), "=r"(r[2]), "=r"(r[3]) : "r"(a));
}
__device__ __forceinline__ void mma16816(float* c, const uint32_t* a, const uint32_t* b) {
    asm volatile(
        "mma.sync.aligned.m16n8k16.row.col.f32.f16.f16.f32 "
        "{%0,%1,%2,%3}, {%4,%5,%6,%7}, {%8,%9}, {%0,%1,%2,%3};"
        : "+f"(c[0]), "+f"(c[1]), "+f"(c[2]), "+f"(c[3])
        : "r"(a[0]), "r"(a[1]), "r"(a[2]), "r"(a[3]), "r"(b[0]), "r"(b[1]));
}
__device__ __forceinline__ uint32_t h2u(__half2 h) {
    return *reinterpret_cast<uint32_t*>(&h);
}
__device__ __forceinline__ void conv8(const float* __restrict__ s, __half* __restrict__ d, int i) {
    const float4* sp = (const float4*)s;
    float4 v0 = sp[2 * i], v1 = sp[2 * i + 1];
    uint4 o;
    o.x = h2u(__floats2half2_rn(v0.x, v0.y));
    o.y = h2u(__floats2half2_rn(v0.z, v0.w));
    o.z = h2u(__floats2half2_rn(v1.x, v1.y));
    o.w = h2u(__floats2half2_rn(v1.z, v1.w));
    ((uint4*)d)[i] = o;
}

// ---------------- sizes ----------------
#define NB_BIG (int)(GATE_SZ / 8 / 256)              // 11264
#define NB_SH  (int)(SH_SZ / 8 / 256)                // 1408

// ---------------- convA: gate/up/sgate/sup conversion + router (+x16 emit) ----------------
__global__ void convA_kernel(const float* __restrict__ gate_w,
                             const float* __restrict__ up_w,
                             const float* __restrict__ sg,
                             const float* __restrict__ su,
                             const float* __restrict__ x,
                             const float* __restrict__ rw) {
    int b = blockIdx.x;
    if (b < NB_BIG) { conv8(gate_w, g_w16, b * 256 + threadIdx.x); return; }
    b -= NB_BIG;
    if (b < NB_BIG) { conv8(up_w, g_w16 + UP_OFF, b * 256 + threadIdx.x); return; }
    b -= NB_BIG;
    if (b < NB_SH)  { conv8(sg, g_w16 + SG_OFF, b * 256 + threadIdx.x); return; }
    b -= NB_SH;
    if (b < NB_SH)  { conv8(su, g_w16 + SU_OFF, b * 256 + threadIdx.x); return; }
    b -= NB_SH;

    // ---- router for token t = b (also emits g_x16 row t) ----
    __shared__ float sx[HID];
    __shared__ float logits[NEXP];
    const int t    = b;
    const int tid  = threadIdx.x;
    const int lane = tid & 31;
    const int wid  = tid >> 5;
    const float4* xr = (const float4*)(x + (size_t)t * HID);
    #pragma unroll
    for (int i = tid; i < HID / 4; i += 256) ((float4*)sx)[i] = xr[i];
    __syncthreads();

    __half2* xo = (__half2*)(g_x16 + (size_t)t * HID);
    #pragma unroll
    for (int i = tid; i < HID / 2; i += 256) {
        float2 v = ((const float2*)sx)[i];
        xo[i] = __floats2half2_rn(v.x, v.y);
    }

    const float* wr = rw + (size_t)wid * HID;
    float s = 0.f;
    for (int i = lane; i < HID; i += 32) s += sx[i] * wr[i];
    #pragma unroll
    for (int o = 16; o; o >>= 1) s += __shfl_xor_sync(0xffffffffu, s, o);
    if (lane == 0) logits[wid] = s;
    __syncthreads();
    if (tid == 0) {
        int i0 = 0; float l0 = logits[0];
        #pragma unroll
        for (int e = 1; e < NEXP; e++) if (logits[e] > l0) { l0 = logits[e]; i0 = e; }
        int i1 = -1; float l1 = -3.4e38f;
        #pragma unroll
        for (int e = 0; e < NEXP; e++) if (e != i0 && logits[e] > l1) { l1 = logits[e]; i1 = e; }
        float r  = expf(l1 - l0);
        float w0 = 1.f / (1.f + r);
        float w1 = 1.f - w0;
        int p0 = atomicAdd(&g_cnt[i0], 1);
        g_tok[i0 * T_TOK + p0] = t; g_slot[i0 * T_TOK + p0] = 2 * t;     g_wt[i0 * T_TOK + p0] = w0;
        int p1 = atomicAdd(&g_cnt[i1], 1);
        g_tok[i1 * T_TOK + p1] = t; g_slot[i1 * T_TOK + p1] = 2 * t + 1; g_wt[i1 * T_TOK + p1] = w1;
    }
}

// ---------------- convD: down + shared_down conversion (runs concurrent with gemm1) ----------------
__global__ void convD_kernel(const float* __restrict__ down_w,
                             const float* __restrict__ sd) {
    int b = blockIdx.x;
    if (b < NB_BIG) conv8(down_w, g_w16 + DOWN_OFF, b * 256 + threadIdx.x);
    else            conv8(sd,     g_w16 + SD_OFF, (b - NB_BIG) * 256 + threadIdx.x);
}

// ---------------- gemm1: CTA 128x64(INTER) dual, BK=64, 3-stage, 256 thr ----------------
#define G1_STAGE 32768
#define G1_SMEM  (3 * G1_STAGE)
#define KB1 (HID / 64)

__global__ void __launch_bounds__(256, 2)
gemm1_f16() {
    extern __shared__ __align__(16) char smem[];
    const int e  = blockIdx.z;
    const int m0 = blockIdx.y * 128;
    const int n0 = blockIdx.x * 64;
    int M; size_t grp;
    const __half *bgp, *bup;
    if (e < NEXP) {
        M = g_cnt[e];
        if (m0 >= M) return;
        bgp = g_w16 + (size_t)e * INTER * HID;
        bup = g_w16 + UP_OFF + (size_t)e * INTER * HID;
        grp = (size_t)e * T_TOK;
    } else {
        M = T_TOK;
        bgp = g_w16 + SG_OFF; bup = g_w16 + SU_OFF;
        grp = (size_t)NEXP * T_TOK;
    }

    __shared__ int tok_s[128];
    const int tid = threadIdx.x, lane = tid & 31, wid = tid >> 5;
    if (tid < 128) {
        int r = m0 + tid;
        tok_s[tid] = (e < NEXP) ? ((r < M) ? g_tok[e * T_TOK + r] : 0) : r;
    }
    __syncthreads();

    const uint32_t sb = smem_u32(smem);

    const int lrow = tid >> 3;           // 0..31
    const int slot = tid & 7;
    const uint32_t aD0 = swz(lrow,      slot * 16);
    const uint32_t aD1 = swz(lrow + 32, slot * 16);
    const uint32_t aD2 = swz(lrow + 64, slot * 16);
    const uint32_t aD3 = swz(lrow + 96, slot * 16);
    const uint32_t bD0 = swz(lrow,      slot * 16);
    const uint32_t bD1 = swz(lrow + 32, slot * 16);
    const __half* aS0 = g_x16 + (size_t)tok_s[lrow]      * HID + slot * 8;
    const __half* aS1 = g_x16 + (size_t)tok_s[lrow + 32] * HID + slot * 8;
    const __half* aS2 = g_x16 + (size_t)tok_s[lrow + 64] * HID + slot * 8;
    const __half* aS3 = g_x16 + (size_t)tok_s[lrow + 96] * HID + slot * 8;
    const __half* gS0 = bgp + (size_t)(n0 + lrow)      * HID + slot * 8;
    const __half* gS1 = bgp + (size_t)(n0 + lrow + 32) * HID + slot * 8;
    const __half* uS0 = bup + (size_t)(n0 + lrow)      * HID + slot * 8;
    const __half* uS1 = bup + (size_t)(n0 + lrow + 32) * HID + slot * 8;

    #define G1_ISSUE(s_, k_) { \
        cpa((s_) + aD0, aS0 + (k_)); cpa((s_) + aD1, aS1 + (k_)); \
        cpa((s_) + aD2, aS2 + (k_)); cpa((s_) + aD3, aS3 + (k_)); \
        cpa((s_) + 16384u + bD0, gS0 + (k_)); cpa((s_) + 16384u + bD1, gS1 + (k_)); \
        cpa((s_) + 24576u + bD0, uS0 + (k_)); cpa((s_) + 24576u + bD1, uS1 + (k_)); }

    const int widl = wid & 3;
    const int wm = (widl & 1) * 64;
    const int wn = (widl >> 1) * 32;
    const uint32_t breg = (wid < 4) ? 16384u : 24576u;
    const int lr   = lane & 7;
    const int arow = ((lane >> 3) & 1) * 8 + lr;
    const int acbx = (lane >> 4) * 16;
    const int brow = (lane >> 4) * 8 + lr;
    const int bcbx = ((lane >> 3) & 1) * 16;

    float c[4][4][4];
    #pragma unroll
    for (int i = 0; i < 4; i++)
        #pragma unroll
        for (int j = 0; j < 4; j++)
            #pragma unroll
            for (int q = 0; q < 4; q++) c[i][j][q] = 0.f;

    const uint32_t st0 = sb, st2 = sb + 2 * G1_STAGE;
    G1_ISSUE(st0, 0);             CP_COMMIT();
    G1_ISSUE(st0 + G1_STAGE, 64); CP_COMMIT();
    uint32_t sc = st0;
    for (int i = 0; i < KB1; i++) {
        CP_WAIT1();
        __syncthreads();
        if (i + 2 < KB1) {
            uint32_t s2 = sc + 2 * G1_STAGE;
            if (s2 > st2) s2 -= 3 * G1_STAGE;
            G1_ISSUE(s2, (i + 2) * 64);
        }
        CP_COMMIT();
        const uint32_t sA = sc;
        const uint32_t sB = sc + breg;
        #pragma unroll
        for (int ks = 0; ks < 4; ks++) {
            const int kb = ks * 32;
            uint32_t a[4][4], b[4][2];
            #pragma unroll
            for (int mt = 0; mt < 4; mt++)
                ldsm4(a[mt], sA + swz(wm + mt * 16 + arow, kb + acbx));
            #pragma unroll
            for (int p = 0; p < 2; p++) {
                uint32_t t4[4];
                ldsm4(t4, sB + swz(wn + p * 16 + brow, kb + bcbx));
                b[2*p][0] = t4[0]; b[2*p][1] = t4[1];
                b[2*p+1][0] = t4[2]; b[2*p+1][1] = t4[3];
            }
            #pragma unroll
            for (int mt = 0; mt < 4; mt++)
                #pragma unroll
                for (int nt = 0; nt < 4; nt++)
                    mma16816(c[mt][nt], a[mt], b[nt]);
        }
        sc = (sc == st2) ? st0 : sc + G1_STAGE;
    }
    __syncthreads();

    __half2* us = (__half2*)smem;   // [128][32] half2 = 16KB
    if (wid >= 4) {
        #pragma unroll
        for (int mt = 0; mt < 4; mt++)
            #pragma unroll
            for (int nt = 0; nt < 4; nt++) {
                int row = wm + mt * 16 + (lane >> 2);
                int c2  = (wn + nt * 8 + 2 * (lane & 3)) >> 1;
                us[row * 32 + c2]       = __floats2half2_rn(c[mt][nt][0], c[mt][nt][1]);
                us[(row + 8) * 32 + c2] = __floats2half2_rn(c[mt][nt][2], c[mt][nt][3]);
            }
    }
    __syncthreads();
    if (wid < 4) {
        __half* hb = g_hmid + grp * INTER;
        #pragma unroll
        for (int mt = 0; mt < 4; mt++)
            #pragma unroll
            for (int nt = 0; nt < 4; nt++) {
                int row  = wm + mt * 16 + (lane >> 2);
                int lcol = wn + nt * 8 + 2 * (lane & 3);
                #pragma unroll
                for (int h = 0; h < 2; h++) {
                    int rr = row + 8 * h;
                    if (m0 + rr < M) {
                        float2 uv = __half22float2(us[rr * 32 + (lcol >> 1)]);
                        float g0 = c[mt][nt][2 * h], g1 = c[mt][nt][2 * h + 1];
                        float h0 = g0 / (1.f + __expf(-g0)) * uv.x;
                        float h1 = g1 / (1.f + __expf(-g1)) * uv.y;
                        *(__half2*)(hb + (size_t)(m0 + rr) * INTER + n0 + lcol) = __floats2half2_rn(h0, h1);
                    }
                }
            }
    }
}

// ---------------- gemm2: CTA 128x128(HID), BK=64, 3-stage, 256 thr ----------------
#define G2_STAGE 32768
#define G2_SMEM  (3 * G2_STAGE)
#define KB2 (INTER / 64)

__global__ void __launch_bounds__(256, 2)
gemm2_f16(float* __restrict__ out) {
    extern __shared__ __align__(16) char smem[];
    const int e  = blockIdx.z;
    const int m0 = blockIdx.y * 128;
    const int n0 = blockIdx.x * 128;
    const int is_shared = (e == NEXP);
    int M; size_t grp;
    const __half* bp;
    if (is_shared) {
        M = T_TOK; grp = (size_t)NEXP * T_TOK; bp = g_w16 + SD_OFF;
    } else {
        M = g_cnt[e];
        if (m0 >= M) return;
        grp = (size_t)e * T_TOK;
        bp  = g_w16 + DOWN_OFF + (size_t)e * HID * INTER;
    }

    __shared__ int   idx_s[128];
    __shared__ float wt_s[128];
    const int tid = threadIdx.x, lane = tid & 31, wid = tid >> 5;
    if (tid < 128) {
        int r = m0 + tid;
        if (is_shared) { idx_s[tid] = r; wt_s[tid] = 1.f; }
        else {
            idx_s[tid] = (r < M) ? g_slot[e * T_TOK + r] : 0;
            wt_s[tid]  = (r < M) ? g_wt  [e * T_TOK + r] : 0.f;
        }
    }
    __syncthreads();

    const uint32_t sb = smem_u32(smem);
    const __half* hb = g_hmid + grp * INTER;

    const int lrow = tid >> 3;
    const int slot = tid & 7;
    const uint32_t dD0 = swz(lrow,      slot * 16);
    const uint32_t dD1 = swz(lrow + 32, slot * 16);
    const uint32_t dD2 = swz(lrow + 64, slot * 16);
    const uint32_t dD3 = swz(lrow + 96, slot * 16);
    int rA0 = m0 + lrow;      if (rA0 >= M) rA0 = m0;
    int rA1 = m0 + 32 + lrow; if (rA1 >= M) rA1 = m0;
    int rA2 = m0 + 64 + lrow; if (rA2 >= M) rA2 = m0;
    int rA3 = m0 + 96 + lrow; if (rA3 >= M) rA3 = m0;
    const __half* aS0 = hb + (size_t)rA0 * INTER + slot * 8;
    const __half* aS1 = hb + (size_t)rA1 * INTER + slot * 8;
    const __half* aS2 = hb + (size_t)rA2 * INTER + slot * 8;
    const __half* aS3 = hb + (size_t)rA3 * INTER + slot * 8;
    const __half* bS0 = bp + (size_t)(n0 + lrow)      * INTER + slot * 8;
    const __half* bS1 = bp + (size_t)(n0 + 32 + lrow) * INTER + slot * 8;
    const __half* bS2 = bp + (size_t)(n0 + 64 + lrow) * INTER + slot * 8;
    const __half* bS3 = bp + (size_t)(n0 + 96 + lrow) * INTER + slot * 8;

    #define G2_ISSUE(s_, k_) { \
        cpa((s_) + dD0, aS0 + (k_)); cpa((s_) + dD1, aS1 + (k_)); \
        cpa((s_) + dD2, aS2 + (k_)); cpa((s_) + dD3, aS3 + (k_)); \
        cpa((s_) + 16384u + dD0, bS0 + (k_)); cpa((s_) + 16384u + dD1, bS1 + (k_)); \
        cpa((s_) + 16384u + dD2, bS2 + (k_)); cpa((s_) + 16384u + dD3, bS3 + (k_)); }

    const int wm = (wid & 1) * 64;
    const int wn = (wid >> 1) * 32;
    const int lr   = lane & 7;
    const int arow = ((lane >> 3) & 1) * 8 + lr;
    const int acbx = (lane >> 4) * 16;
    const int brow = (lane >> 4) * 8 + lr;
    const int bcbx = ((lane >> 3) & 1) * 16;

    float c[4][4][4];
    #pragma unroll
    for (int i = 0; i < 4; i++)
        #pragma unroll
        for (int j = 0; j < 4; j++)
            #pragma unroll
            for (int q = 0; q < 4; q++) c[i][j][q] = 0.f;

    const uint32_t st0 = sb, st2 = sb + 2 * G2_STAGE;
    G2_ISSUE(st0, 0);             CP_COMMIT();
    G2_ISSUE(st0 + G2_STAGE, 64); CP_COMMIT();
    uint32_t sc = st0;
    for (int i = 0; i < KB2; i++) {
        CP_WAIT1();
        __syncthreads();
        if (i + 2 < KB2) {
            uint32_t s2 = sc + 2 * G2_STAGE;
            if (s2 > st2) s2 -= 3 * G2_STAGE;
            G2_ISSUE(s2, (i + 2) * 64);
        }
        CP_COMMIT();
        const uint32_t sA = sc;
        const uint32_t sB = sc + 16384u;
        #pragma unroll
        for (int ks = 0; ks < 4; ks++) {
            const int kb = ks * 32;
            uint32_t a[4][4], b[4][2];
            #pragma unroll
            for (int mt = 0; mt < 4; mt++)
                ldsm4(a[mt], sA + swz(wm + mt * 16 + arow, kb + acbx));
            #pragma unroll
            for (int p = 0; p < 2; p++) {
                uint32_t t4[4];
                ldsm4(t4, sB + swz(wn + p * 16 + brow, kb + bcbx));
                b[2*p][0] = t4[0]; b[2*p][1] = t4[1];
                b[2*p+1][0] = t4[2]; b[2*p+1][1] = t4[3];
            }
            #pragma unroll
            for (int mt = 0; mt < 4; mt++)
                #pragma unroll
                for (int nt = 0; nt < 4; nt++)
                    mma16816(c[mt][nt], a[mt], b[nt]);
        }
        sc = (sc == st2) ? st0 : sc + G2_STAGE;
    }

    float* obase = is_shared ? out : g_eo;
    #pragma unroll
    for (int mt = 0; mt < 4; mt++)
        #pragma unroll
        for (int nt = 0; nt < 4; nt++) {
            int row  = wm + mt * 16 + (lane >> 2);
            int gcol = n0 + wn + nt * 8 + 2 * (lane & 3);
            #pragma unroll
            for (int h = 0; h < 2; h++) {
                int rr = row + 8 * h;
                if (m0 + rr < M) {
                    float w  = wt_s[rr];
                    int   sl = idx_s[rr];
                    float2 o;
                    o.x = w * c[mt][nt][2 * h];
                    o.y = w * c[mt][nt][2 * h + 1];
                    *(float2*)(obase + (size_t)sl * HID + gcol) = o;
                }
            }
        }
}

// ---------------- combine (+ reset g_cnt for the next graph replay) ----------------
__global__ void combine_kernel(float* __restrict__ out) {
    if (blockIdx.x == 0 && threadIdx.x < NEXP) g_cnt[threadIdx.x] = 0;
    int idx = blockIdx.x * blockDim.x + threadIdx.x;
    const int W = HID / 4;
    int t  = idx / W;
    int h4 = idx - t * W;
    float4 o = ((float4*)out)[idx];
    float4 a = ((const float4*)g_eo)[(size_t)(2 * t)     * W + h4];
    float4 b = ((const float4*)g_eo)[(size_t)(2 * t + 1) * W + h4];
    o.x += a.x + b.x; o.y += a.y + b.y; o.z += a.z + b.z; o.w += a.w + b.w;
    ((float4*)out)[idx] = o;
}

// ---------------- launch ----------------
extern "C" void kernel_launch(void* const* d_in, const int* in_sizes, int n_in,
                              void* d_out, int out_size) {
    const float* x        = (const float*)d_in[0];
    const float* router_w = (const float*)d_in[1];
    const float* gate_w   = (const float*)d_in[2];
    const float* up_w     = (const float*)d_in[3];
    const float* down_w   = (const float*)d_in[4];
    const float* sgate    = (const float*)d_in[5];
    const float* sup      = (const float*)d_in[6];
    const float* sdown    = (const float*)d_in[7];
    float* out = (float*)d_out;

    static cudaStream_t s2 = nullptr;
    static cudaEvent_t evFork = nullptr, evJoin = nullptr;
    if (!s2) {
        cudaStreamCreateWithFlags(&s2, cudaStreamNonBlocking);
        cudaEventCreateWithFlags(&evFork, cudaEventDisableTiming);
        cudaEventCreateWithFlags(&evJoin, cudaEventDisableTiming);
        cudaFuncSetAttribute(gemm1_f16, cudaFuncAttributeMaxDynamicSharedMemorySize, G1_SMEM);
        cudaFuncSetAttribute(gemm2_f16, cudaFuncAttributeMaxDynamicSharedMemorySize, G2_SMEM);
    }

    // main stream: convA (gate/up/shared-gu + router)  ... gemm1
    convA_kernel<<<2 * NB_BIG + 2 * NB_SH + T_TOK, 256>>>(
        gate_w, up_w, sgate, sup, x, router_w);
    // fork: convD runs on s2 concurrently with gemm1 (no dependency between them)
    cudaEventRecord(evFork, 0);
    cudaStreamWaitEvent(s2, evFork, 0);
    convD_kernel<<<NB_BIG + NB_SH, 256, 0, s2>>>(down_w, sdown);
    gemm1_f16<<<dim3(INTER / 64, T_TOK / 128, NEXP + 1), 256, G1_SMEM>>>();
    // join: gemm2 needs down weights
    cudaEventRecord(evJoin, s2);
    cudaStreamWaitEvent(0, evJoin, 0);
    gemm2_f16<<<dim3(HID / 128, T_TOK / 128, NEXP + 1), 256, G2_SMEM>>>(out);
    combine_kernel<<<(T_TOK * HID / 4) / 256, 256>>>(out);
}

// round 14
// speedup vs baseline: 1.0111x; 1.0111x over previous
#include <cuda_runtime.h>
#include <cuda_fp16.h>
#include <cstdint>
#include <math.h>

#define T_TOK 2048
#define HID   2048
#define INTER 1408
#define NEXP  8

#define GATE_SZ ((size_t)NEXP * INTER * HID)
#define SH_SZ   ((size_t)INTER * HID)
#define UP_OFF   (GATE_SZ)
#define DOWN_OFF (2 * GATE_SZ)
#define SG_OFF   (3 * GATE_SZ)
#define SU_OFF   (SG_OFF + SH_SZ)
#define SD_OFF   (SU_OFF + SH_SZ)
#define W16_TOTAL (SD_OFF + SH_SZ)

// ---------------- device scratch ----------------
__device__ __half g_w16[W16_TOTAL];
__device__ __half g_x16[(size_t)T_TOK * HID];
__device__ __half g_hmid[(size_t)(NEXP + 1) * T_TOK * INTER];
__device__ int    g_cnt[NEXP];          // zero-init at load; re-zeroed by combine tail
__device__ int    g_tok [NEXP * T_TOK];
__device__ int    g_slot[NEXP * T_TOK];
__device__ float  g_wt  [NEXP * T_TOK];
__device__ __half g_eo  [(size_t)2 * T_TOK * HID];   // fp16 routed partials

// ---------------- helpers ----------------
__device__ __forceinline__ uint32_t smem_u32(const void* p) {
    uint32_t a;
    asm("{ .reg .u64 t; cvta.to.shared.u64 t, %1; cvt.u32.u64 %0, t; }" : "=r"(a) : "l"(p));
    return a;
}
// 128B-row tile swizzle: 16B slot XOR (row&7) — conflict-free cp.async + ldmatrix
__device__ __forceinline__ uint32_t swz(int r, int cb) {
    return (uint32_t)((r << 7) + ((((cb >> 4) ^ (r & 7)) << 4) | (cb & 15)));
}
__device__ __forceinline__ void cpa(uint32_t dst, const void* src) {
    asm volatile("cp.async.cg.shared.global [%0], [%1], 16;" :: "r"(dst), "l"(src));
}
#define CP_COMMIT()  asm volatile("cp.async.commit_group;")
#define CP_WAIT1()   asm volatile("cp.async.wait_group 1;")

__device__ __forceinline__ void ldsm4(uint32_t* r, uint32_t a) {
    asm volatile("ldmatrix.sync.aligned.m8n8.x4.shared.b16 {%0,%1,%2,%3}, [%4];"
        : "=r"(r[0]), "=r"(r[1]), "=r"(r[2]), "=r"(r[3]) : "r"(a));
}
__device__ __forceinline__ void mma16816(float* c, const uint32_t* a, const uint32_t* b) {
    asm volatile(
        "mma.sync.aligned.m16n8k16.row.col.f32.f16.f16.f32 "
        "{%0,%1,%2,%3}, {%4,%5,%6,%7}, {%8,%9}, {%0,%1,%2,%3};"
        : "+f"(c[0]), "+f"(c[1]), "+f"(c[2]), "+f"(c[3])
        : "r"(a[0]), "r"(a[1]), "r"(a[2]), "r"(a[3]), "r"(b[0]), "r"(b[1]));
}
__device__ __forceinline__ uint32_t h2u(__half2 h) {
    return *reinterpret_cast<uint32_t*>(&h);
}
__device__ __forceinline__ void conv8(const float* __restrict__ s, __half* __restrict__ d, int i) {
    const float4* sp = (const float4*)s;
    float4 v0 = sp[2 * i], v1 = sp[2 * i + 1];
    uint4 o;
    o.x = h2u(__floats2half2_rn(v0.x, v0.y));
    o.y = h2u(__floats2half2_rn(v0.z, v0.w));
    o.z = h2u(__floats2half2_rn(v1.x, v1.y));
    o.w = h2u(__floats2half2_rn(v1.z, v1.w));
    ((uint4*)d)[i] = o;
}

// ---------------- sizes ----------------
#define NB_BIG (int)(GATE_SZ / 8 / 256)              // 11264
#define NB_SH  (int)(SH_SZ / 8 / 256)                // 1408

// ---------------- conv_all: every weight conversion + router (+x16 emit) ----------------
__global__ void conv_router_kernel(const float* __restrict__ gate_w,
                                   const float* __restrict__ up_w,
                                   const float* __restrict__ down_w,
                                   const float* __restrict__ sg,
                                   const float* __restrict__ su,
                                   const float* __restrict__ sd,
                                   const float* __restrict__ x,
                                   const float* __restrict__ rw) {
    int b = blockIdx.x;
    if (b < NB_BIG) { conv8(gate_w, g_w16, b * 256 + threadIdx.x); return; }
    b -= NB_BIG;
    if (b < NB_BIG) { conv8(up_w, g_w16 + UP_OFF, b * 256 + threadIdx.x); return; }
    b -= NB_BIG;
    if (b < NB_BIG) { conv8(down_w, g_w16 + DOWN_OFF, b * 256 + threadIdx.x); return; }
    b -= NB_BIG;
    if (b < NB_SH)  { conv8(sg, g_w16 + SG_OFF, b * 256 + threadIdx.x); return; }
    b -= NB_SH;
    if (b < NB_SH)  { conv8(su, g_w16 + SU_OFF, b * 256 + threadIdx.x); return; }
    b -= NB_SH;
    if (b < NB_SH)  { conv8(sd, g_w16 + SD_OFF, b * 256 + threadIdx.x); return; }
    b -= NB_SH;

    // ---- router for token t = b (also emits g_x16 row t) ----
    __shared__ float sx[HID];
    __shared__ float logits[NEXP];
    const int t    = b;
    const int tid  = threadIdx.x;
    const int lane = tid & 31;
    const int wid  = tid >> 5;
    const float4* xr = (const float4*)(x + (size_t)t * HID);
    #pragma unroll
    for (int i = tid; i < HID / 4; i += 256) ((float4*)sx)[i] = xr[i];
    __syncthreads();

    __half2* xo = (__half2*)(g_x16 + (size_t)t * HID);
    #pragma unroll
    for (int i = tid; i < HID / 2; i += 256) {
        float2 v = ((const float2*)sx)[i];
        xo[i] = __floats2half2_rn(v.x, v.y);
    }

    const float* wr = rw + (size_t)wid * HID;
    float s = 0.f;
    for (int i = lane; i < HID; i += 32) s += sx[i] * wr[i];
    #pragma unroll
    for (int o = 16; o; o >>= 1) s += __shfl_xor_sync(0xffffffffu, s, o);
    if (lane == 0) logits[wid] = s;
    __syncthreads();
    if (tid == 0) {
        int i0 = 0; float l0 = logits[0];
        #pragma unroll
        for (int e = 1; e < NEXP; e++) if (logits[e] > l0) { l0 = logits[e]; i0 = e; }
        int i1 = -1; float l1 = -3.4e38f;
        #pragma unroll
        for (int e = 0; e < NEXP; e++) if (e != i0 && logits[e] > l1) { l1 = logits[e]; i1 = e; }
        float r  = expf(l1 - l0);
        float w0 = 1.f / (1.f + r);
        float w1 = 1.f - w0;
        int p0 = atomicAdd(&g_cnt[i0], 1);
        g_tok[i0 * T_TOK + p0] = t; g_slot[i0 * T_TOK + p0] = 2 * t;     g_wt[i0 * T_TOK + p0] = w0;
        int p1 = atomicAdd(&g_cnt[i1], 1);
        g_tok[i1 * T_TOK + p1] = t; g_slot[i1 * T_TOK + p1] = 2 * t + 1; g_wt[i1 * T_TOK + p1] = w1;
    }
}

// ---------------- gemm1: CTA 128x64(INTER) dual, BK=64, 3-stage, 256 thr ----------------
#define G1_STAGE 32768
#define G1_SMEM  (3 * G1_STAGE)
#define KB1 (HID / 64)

__global__ void __launch_bounds__(256, 2)
gemm1_f16() {
    extern __shared__ __align__(16) char smem[];
    const int e  = blockIdx.z;
    const int m0 = blockIdx.y * 128;
    const int n0 = blockIdx.x * 64;
    int M; size_t grp;
    const __half *bgp, *bup;
    if (e < NEXP) {
        M = g_cnt[e];
        if (m0 >= M) return;
        bgp = g_w16 + (size_t)e * INTER * HID;
        bup = g_w16 + UP_OFF + (size_t)e * INTER * HID;
        grp = (size_t)e * T_TOK;
    } else {
        M = T_TOK;
        bgp = g_w16 + SG_OFF; bup = g_w16 + SU_OFF;
        grp = (size_t)NEXP * T_TOK;
    }

    __shared__ int tok_s[128];
    const int tid = threadIdx.x, lane = tid & 31, wid = tid >> 5;
    if (tid < 128) {
        int r = m0 + tid;
        tok_s[tid] = (e < NEXP) ? ((r < M) ? g_tok[e * T_TOK + r] : 0) : r;
    }
    __syncthreads();

    const uint32_t sb = smem_u32(smem);

    const int lrow = tid >> 3;           // 0..31
    const int slot = tid & 7;
    const uint32_t aD0 = swz(lrow,      slot * 16);
    const uint32_t aD1 = swz(lrow + 32, slot * 16);
    const uint32_t aD2 = swz(lrow + 64, slot * 16);
    const uint32_t aD3 = swz(lrow + 96, slot * 16);
    const uint32_t bD0 = swz(lrow,      slot * 16);
    const uint32_t bD1 = swz(lrow + 32, slot * 16);
    const __half* aS0 = g_x16 + (size_t)tok_s[lrow]      * HID + slot * 8;
    const __half* aS1 = g_x16 + (size_t)tok_s[lrow + 32] * HID + slot * 8;
    const __half* aS2 = g_x16 + (size_t)tok_s[lrow + 64] * HID + slot * 8;
    const __half* aS3 = g_x16 + (size_t)tok_s[lrow + 96] * HID + slot * 8;
    const __half* gS0 = bgp + (size_t)(n0 + lrow)      * HID + slot * 8;
    const __half* gS1 = bgp + (size_t)(n0 + lrow + 32) * HID + slot * 8;
    const __half* uS0 = bup + (size_t)(n0 + lrow)      * HID + slot * 8;
    const __half* uS1 = bup + (size_t)(n0 + lrow + 32) * HID + slot * 8;

    #define G1_ISSUE(s_, k_) { \
        cpa((s_) + aD0, aS0 + (k_)); cpa((s_) + aD1, aS1 + (k_)); \
        cpa((s_) + aD2, aS2 + (k_)); cpa((s_) + aD3, aS3 + (k_)); \
        cpa((s_) + 16384u + bD0, gS0 + (k_)); cpa((s_) + 16384u + bD1, gS1 + (k_)); \
        cpa((s_) + 24576u + bD0, uS0 + (k_)); cpa((s_) + 24576u + bD1, uS1 + (k_)); }

    const int widl = wid & 3;
    const int wm = (widl & 1) * 64;
    const int wn = (widl >> 1) * 32;
    const uint32_t breg = (wid < 4) ? 16384u : 24576u;
    const int lr   = lane & 7;
    const int arow = ((lane >> 3) & 1) * 8 + lr;
    const int acbx = (lane >> 4) * 16;
    const int brow = (lane >> 4) * 8 + lr;
    const int bcbx = ((lane >> 3) & 1) * 16;

    float c[4][4][4];
    #pragma unroll
    for (int i = 0; i < 4; i++)
        #pragma unroll
        for (int j = 0; j < 4; j++)
            #pragma unroll
            for (int q = 0; q < 4; q++) c[i][j][q] = 0.f;

    const uint32_t st0 = sb, st2 = sb + 2 * G1_STAGE;
    G1_ISSUE(st0, 0);             CP_COMMIT();
    G1_ISSUE(st0 + G1_STAGE, 64); CP_COMMIT();
    uint32_t sc = st0;
    for (int i = 0; i < KB1; i++) {
        CP_WAIT1();
        __syncthreads();
        if (i + 2 < KB1) {
            uint32_t s2 = sc + 2 * G1_STAGE;
            if (s2 > st2) s2 -= 3 * G1_STAGE;
            G1_ISSUE(s2, (i + 2) * 64);
        }
        CP_COMMIT();
        const uint32_t sA = sc;
        const uint32_t sB = sc + breg;
        #pragma unroll
        for (int ks = 0; ks < 4; ks++) {
            const int kb = ks * 32;
            uint32_t a[4][4], b[4][2];
            #pragma unroll
            for (int mt = 0; mt < 4; mt++)
                ldsm4(a[mt], sA + swz(wm + mt * 16 + arow, kb + acbx));
            #pragma unroll
            for (int p = 0; p < 2; p++) {
                uint32_t t4[4];
                ldsm4(t4, sB + swz(wn + p * 16 + brow, kb + bcbx));
                b[2*p][0] = t4[0]; b[2*p][1] = t4[1];
                b[2*p+1][0] = t4[2]; b[2*p+1][1] = t4[3];
            }
            #pragma unroll
            for (int mt = 0; mt < 4; mt++)
                #pragma unroll
                for (int nt = 0; nt < 4; nt++)
                    mma16816(c[mt][nt], a[mt], b[nt]);
        }
        sc = (sc == st2) ? st0 : sc + G1_STAGE;
    }
    __syncthreads();

    __half2* us = (__half2*)smem;   // [128][32] half2 = 16KB
    if (wid >= 4) {
        #pragma unroll
        for (int mt = 0; mt < 4; mt++)
            #pragma unroll
            for (int nt = 0; nt < 4; nt++) {
                int row = wm + mt * 16 + (lane >> 2);
                int c2  = (wn + nt * 8 + 2 * (lane & 3)) >> 1;
                us[row * 32 + c2]       = __floats2half2_rn(c[mt][nt][0], c[mt][nt][1]);
                us[(row + 8) * 32 + c2] = __floats2half2_rn(c[mt][nt][2], c[mt][nt][3]);
            }
    }
    __syncthreads();
    if (wid < 4) {
        __half* hb = g_hmid + grp * INTER;
        #pragma unroll
        for (int mt = 0; mt < 4; mt++)
            #pragma unroll
            for (int nt = 0; nt < 4; nt++) {
                int row  = wm + mt * 16 + (lane >> 2);
                int lcol = wn + nt * 8 + 2 * (lane & 3);
                #pragma unroll
                for (int h = 0; h < 2; h++) {
                    int rr = row + 8 * h;
                    if (m0 + rr < M) {
                        float2 uv = __half22float2(us[rr * 32 + (lcol >> 1)]);
                        float g0 = c[mt][nt][2 * h], g1 = c[mt][nt][2 * h + 1];
                        float h0 = g0 / (1.f + __expf(-g0)) * uv.x;
                        float h1 = g1 / (1.f + __expf(-g1)) * uv.y;
                        *(__half2*)(hb + (size_t)(m0 + rr) * INTER + n0 + lcol) = __floats2half2_rn(h0, h1);
                    }
                }
            }
    }
}

// ---------------- gemm2: CTA 128x128(HID), BK=64, 3-stage, 256 thr ----------------
#define G2_STAGE 32768
#define G2_SMEM  (3 * G2_STAGE)
#define KB2 (INTER / 64)

__global__ void __launch_bounds__(256, 2)
gemm2_f16(float* __restrict__ out) {
    extern __shared__ __align__(16) char smem[];
    const int e  = blockIdx.z;
    const int m0 = blockIdx.y * 128;
    const int n0 = blockIdx.x * 128;
    const int is_shared = (e == NEXP);
    int M; size_t grp;
    const __half* bp;
    if (is_shared) {
        M = T_TOK; grp = (size_t)NEXP * T_TOK; bp = g_w16 + SD_OFF;
    } else {
        M = g_cnt[e];
        if (m0 >= M) return;
        grp = (size_t)e * T_TOK;
        bp  = g_w16 + DOWN_OFF + (size_t)e * HID * INTER;
    }

    __shared__ int   idx_s[128];
    __shared__ float wt_s[128];
    const int tid = threadIdx.x, lane = tid & 31, wid = tid >> 5;
    if (tid < 128) {
        int r = m0 + tid;
        if (is_shared) { idx_s[tid] = r; wt_s[tid] = 1.f; }
        else {
            idx_s[tid] = (r < M) ? g_slot[e * T_TOK + r] : 0;
            wt_s[tid]  = (r < M) ? g_wt  [e * T_TOK + r] : 0.f;
        }
    }
    __syncthreads();

    const uint32_t sb = smem_u32(smem);
    const __half* hb = g_hmid + grp * INTER;

    const int lrow = tid >> 3;
    const int slot = tid & 7;
    const uint32_t dD0 = swz(lrow,      slot * 16);
    const uint32_t dD1 = swz(lrow + 32, slot * 16);
    const uint32_t dD2 = swz(lrow + 64, slot * 16);
    const uint32_t dD3 = swz(lrow + 96, slot * 16);
    int rA0 = m0 + lrow;      if (rA0 >= M) rA0 = m0;
    int rA1 = m0 + 32 + lrow; if (rA1 >= M) rA1 = m0;
    int rA2 = m0 + 64 + lrow; if (rA2 >= M) rA2 = m0;
    int rA3 = m0 + 96 + lrow; if (rA3 >= M) rA3 = m0;
    const __half* aS0 = hb + (size_t)rA0 * INTER + slot * 8;
    const __half* aS1 = hb + (size_t)rA1 * INTER + slot * 8;
    const __half* aS2 = hb + (size_t)rA2 * INTER + slot * 8;
    const __half* aS3 = hb + (size_t)rA3 * INTER + slot * 8;
    const __half* bS0 = bp + (size_t)(n0 + lrow)      * INTER + slot * 8;
    const __half* bS1 = bp + (size_t)(n0 + 32 + lrow) * INTER + slot * 8;
    const __half* bS2 = bp + (size_t)(n0 + 64 + lrow) * INTER + slot * 8;
    const __half* bS3 = bp + (size_t)(n0 + 96 + lrow) * INTER + slot * 8;

    #define G2_ISSUE(s_, k_) { \
        cpa((s_) + dD0, aS0 + (k_)); cpa((s_) + dD1, aS1 + (k_)); \
        cpa((s_) + dD2, aS2 + (k_)); cpa((s_) + dD3, aS3 + (k_)); \
        cpa((s_) + 16384u + dD0, bS0 + (k_)); cpa((s_) + 16384u + dD1, bS1 + (k_)); \
        cpa((s_) + 16384u + dD2, bS2 + (k_)); cpa((s_) + 16384u + dD3, bS3 + (k_)); }

    const int wm = (wid & 1) * 64;
    const int wn = (wid >> 1) * 32;
    const int lr   = lane & 7;
    const int arow = ((lane >> 3) & 1) * 8 + lr;
    const int acbx = (lane >> 4) * 16;
    const int brow = (lane >> 4) * 8 + lr;
    const int bcbx = ((lane >> 3) & 1) * 16;

    float c[4][4][4];
    #pragma unroll
    for (int i = 0; i < 4; i++)
        #pragma unroll
        for (int j = 0; j < 4; j++)
            #pragma unroll
            for (int q = 0; q < 4; q++) c[i][j][q] = 0.f;

    const uint32_t st0 = sb, st2 = sb + 2 * G2_STAGE;
    G2_ISSUE(st0, 0);             CP_COMMIT();
    G2_ISSUE(st0 + G2_STAGE, 64); CP_COMMIT();
    uint32_t sc = st0;
    for (int i = 0; i < KB2; i++) {
        CP_WAIT1();
        __syncthreads();
        if (i + 2 < KB2) {
            uint32_t s2 = sc + 2 * G2_STAGE;
            if (s2 > st2) s2 -= 3 * G2_STAGE;
            G2_ISSUE(s2, (i + 2) * 64);
        }
        CP_COMMIT();
        const uint32_t sA = sc;
        const uint32_t sB = sc + 16384u;
        #pragma unroll
        for (int ks = 0; ks < 4; ks++) {
            const int kb = ks * 32;
            uint32_t a[4][4], b[4][2];
            #pragma unroll
            for (int mt = 0; mt < 4; mt++)
                ldsm4(a[mt], sA + swz(wm + mt * 16 + arow, kb + acbx));
            #pragma unroll
            for (int p = 0; p < 2; p++) {
                uint32_t t4[4];
                ldsm4(t4, sB + swz(wn + p * 16 + brow, kb + bcbx));
                b[2*p][0] = t4[0]; b[2*p][1] = t4[1];
                b[2*p+1][0] = t4[2]; b[2*p+1][1] = t4[3];
            }
            #pragma unroll
            for (int mt = 0; mt < 4; mt++)
                #pragma unroll
                for (int nt = 0; nt < 4; nt++)
                    mma16816(c[mt][nt], a[mt], b[nt]);
        }
        sc = (sc == st2) ? st0 : sc + G2_STAGE;
    }

    #pragma unroll
    for (int mt = 0; mt < 4; mt++)
        #pragma unroll
        for (int nt = 0; nt < 4; nt++) {
            int row  = wm + mt * 16 + (lane >> 2);
            int gcol = n0 + wn + nt * 8 + 2 * (lane & 3);
            #pragma unroll
            for (int h = 0; h < 2; h++) {
                int rr = row + 8 * h;
                if (m0 + rr < M) {
                    float w  = wt_s[rr];
                    int   sl = idx_s[rr];
                    if (is_shared) {
                        float2 o;
                        o.x = c[mt][nt][2 * h];
                        o.y = c[mt][nt][2 * h + 1];
                        *(float2*)(out + (size_t)sl * HID + gcol) = o;
                    } else {
                        *(__half2*)(g_eo + (size_t)sl * HID + gcol) =
                            __floats2half2_rn(w * c[mt][nt][2 * h], w * c[mt][nt][2 * h + 1]);
                    }
                }
            }
        }
}

// ---------------- combine (+ reset g_cnt for the next graph replay) ----------------
__global__ void combine_kernel(float* __restrict__ out) {
    if (blockIdx.x == 0 && threadIdx.x < NEXP) g_cnt[threadIdx.x] = 0;
    int idx = blockIdx.x * blockDim.x + threadIdx.x;      // float4 index into out
    const int W = HID / 4;
    int t  = idx / W;
    int h4 = idx - t * W;
    float4 o = ((float4*)out)[idx];
    // eo slots are fp16: read 4 halves (= 2 half2 packed in uint2) per slot
    const uint2* e0p = (const uint2*)(g_eo + (size_t)(2 * t)     * HID + h4 * 4);
    const uint2* e1p = (const uint2*)(g_eo + (size_t)(2 * t + 1) * HID + h4 * 4);
    uint2 u0 = *e0p, u1 = *e1p;
    float2 a0 = __half22float2(*(const __half2*)&u0.x);
    float2 a1 = __half22float2(*(const __half2*)&u0.y);
    float2 b0 = __half22float2(*(const __half2*)&u1.x);
    float2 b1 = __half22float2(*(const __half2*)&u1.y);
    o.x += a0.x + b0.x;
    o.y += a0.y + b0.y;
    o.z += a1.x + b1.x;
    o.w += a1.y + b1.y;
    ((float4*)out)[idx] = o;
}

// ---------------- launch ----------------
extern "C" void kernel_launch(void* const* d_in, const int* in_sizes, int n_in,
                              void* d_out, int out_size) {
    const float* x        = (const float*)d_in[0];
    const float* router_w = (const float*)d_in[1];
    const float* gate_w   = (const float*)d_in[2];
    const float* up_w     = (const float*)d_in[3];
    const float* down_w   = (const float*)d_in[4];
    const float* sgate    = (const float*)d_in[5];
    const float* sup      = (const float*)d_in[6];
    const float* sdown    = (const float*)d_in[7];
    float* out = (float*)d_out;

    cudaFuncSetAttribute(gemm1_f16, cudaFuncAttributeMaxDynamicSharedMemorySize, G1_SMEM);
    cudaFuncSetAttribute(gemm2_f16, cudaFuncAttributeMaxDynamicSharedMemorySize, G2_SMEM);

    conv_router_kernel<<<3 * NB_BIG + 3 * NB_SH + T_TOK, 256>>>(
        gate_w, up_w, down_w, sgate, sup, sdown, x, router_w);                   // 1
    gemm1_f16<<<dim3(INTER / 64, T_TOK / 128, NEXP + 1), 256, G1_SMEM>>>();      // 2
    gemm2_f16<<<dim3(HID / 128, T_TOK / 128, NEXP + 1), 256, G2_SMEM>>>(out);    // 3
    combine_kernel<<<(T_TOK * HID / 4) / 256, 256>>>(out);                       // 4
}